// round 4
// baseline (speedup 1.0000x reference)
#include <cuda_runtime.h>
#include <cuda_bf16.h>

// Problem dims (fixed): N=64, C=Cin=256, O=Cout=256, T=64, V=25, TV=1600
#define NB   64
#define CC   256
#define OO   256
#define TT   64
#define VV   25
#define TV   1600
#define NTV  102400   // N*T*V elements per channel

// ---------------- scratch (device globals; no cudaMalloc allowed) ------------
__device__ float g_h2[(size_t)NB * OO * TV];   // relu(conv) output, 104.9 MB
__device__ float g_WpT[CC * OO];               // W'[c][o] = w[o][c]*a_c (transposed)
__device__ float g_aC[CC], g_dC[CC];           // BN1 fold: a, d per input channel
__device__ float g_bias2[OO * TT];             // conv bias + shift-mask correction
__device__ int   g_idx_in[CC * TT];
__device__ float g_frac_in[CC * TT];
__device__ int   g_idx_out[OO * TT];
__device__ float g_frac_out[OO * TT];
__device__ float g_dm[CC * TT];                // d_c * mask(c,t)
__device__ float g_A2[OO], g_D2[OO];           // BN2 scale/shift

// ---------------- packed f32x2 helpers (Blackwell 2xFP32) --------------------
__device__ __forceinline__ void fma2(unsigned long long& d,
                                     unsigned long long a,
                                     unsigned long long b) {
    asm("fma.rn.f32x2 %0, %1, %2, %3;" : "=l"(d) : "l"(a), "l"(b), "l"(d));
}
__device__ __forceinline__ unsigned long long pack2(float lo, float hi) {
    unsigned long long r;
    asm("mov.b64 %0, {%1, %2};" : "=l"(r) : "f"(lo), "f"(hi));
    return r;
}
__device__ __forceinline__ float2 unpack2(unsigned long long v) {
    float2 r;
    asm("mov.b64 {%0, %1}, %2;" : "=f"(r.x), "=f"(r.y) : "l"(v));
    return r;
}

// ---------------- kernel 1: per-channel stats of x -> a_c, d_c ---------------
__global__ void stats_x_kernel(const float* __restrict__ x,
                               const float* __restrict__ g1,
                               const float* __restrict__ b1) {
    const int c = blockIdx.x;
    float s = 0.f, ss = 0.f;
    for (int n = 0; n < NB; ++n) {
        const float* row = x + ((size_t)n * CC + c) * TV;
        for (int i = threadIdx.x; i < TV; i += 256) {
            float v = row[i];
            s += v; ss += v * v;
        }
    }
    __shared__ float sh1[256], sh2[256];
    sh1[threadIdx.x] = s; sh2[threadIdx.x] = ss;
    __syncthreads();
    for (int off = 128; off > 0; off >>= 1) {
        if (threadIdx.x < off) {
            sh1[threadIdx.x] += sh1[threadIdx.x + off];
            sh2[threadIdx.x] += sh2[threadIdx.x + off];
        }
        __syncthreads();
    }
    if (threadIdx.x == 0) {
        float mean = sh1[0] / (float)NTV;
        float var  = sh2[0] / (float)NTV - mean * mean;
        float a = g1[c] * rsqrtf(var + 1e-5f);
        g_aC[c] = a;
        g_dC[c] = b1[c] - mean * a;
    }
}

// ---------------- kernel 2: shift tables (exact JAX floor semantics) ---------
__global__ void tables_kernel(const float* __restrict__ th_in,
                              const float* __restrict__ th_out) {
    int gid = blockIdx.x * blockDim.x + threadIdx.x;
    if (gid >= CC * TT) return;
    int c = gid >> 6, t = gid & 63;
    {
        float pos = (float)t + th_in[c];
        float fl = floorf(pos);
        int i0 = (int)fl;
        float fr = pos - fl;
        g_idx_in[gid] = i0;
        g_frac_in[gid] = fr;
        float m = ((i0 >= 0 && i0 < TT) ? (1.f - fr) : 0.f)
                + ((i0 + 1 >= 0 && i0 + 1 < TT) ? fr : 0.f);
        g_dm[gid] = g_dC[c] * m;
    }
    {
        float pos = (float)t + th_out[c];
        float fl = floorf(pos);
        int i0 = (int)fl;
        float fr = pos - fl;
        g_idx_out[gid] = i0;
        g_frac_out[gid] = fr;
    }
}

// ---------------- kernel 3: W' transposed with BN1 scale folded --------------
__global__ void wprep_kernel(const float* __restrict__ w) {
    int o = blockIdx.x, c = threadIdx.x;
    g_WpT[c * OO + o] = w[o * CC + c] * g_aC[c];
}

// ---------------- kernel 4: bias2[o][t] = conv_b + sum_c w*d_c*m(c,t) --------
__global__ void bias_kernel(const float* __restrict__ w,
                            const float* __restrict__ cb) {
    int o = blockIdx.x, t = threadIdx.x;  // 64 threads
    float s = 0.f;
    for (int c = 0; c < CC; ++c)
        s += w[o * CC + c] * g_dm[c * TT + t];
    g_bias2[o * TT + t] = cb[o] + s;
}

// ---------------- kernel 5: fused shift_in + GEMM + bias + ReLU --------------
// h2[n,o,tv] = relu( sum_c W'[o,c] * sx[n,c,tv] + bias2[o, t(tv)] )
// Tile: 128(O) x 64(TV) x 16(K), 256 threads, 8x4 outputs/thread,
// packed f32x2 FMA along the M dimension.
__global__ void __launch_bounds__(256, 2)
gemm_kernel(const float* __restrict__ x) {
    __shared__ float As[16][128];  // A[k][o]
    __shared__ float Bs[16][64];   // B[k][j]

    const int tid = threadIdx.x;
    const int n   = blockIdx.z;
    const int o0  = blockIdx.y * 128;
    const int tv0 = blockIdx.x * 64;

    // B-loader fixed coordinates (one column per thread, 4 K-rows per pass)
    const int jb  = tid & 63;
    const int cb0 = tid >> 6;                // 0..3
    const int tvb = tv0 + jb;
    const int tb  = tvb / 25;
    const int vb  = tvb - tb * 25;
    const float* xn = x + (size_t)n * CC * TV;

    // A-loader coordinates (float4)
    const int oa = (tid & 31) * 4;
    const int ka = tid >> 5;                 // 0..7

    // compute mapping
    const int tx = tid & 15;
    const int ty = tid >> 4;

    unsigned long long acc[4][4];
#pragma unroll
    for (int m = 0; m < 4; ++m)
#pragma unroll
        for (int j = 0; j < 4; ++j) acc[m][j] = 0ull;

    for (int k0 = 0; k0 < CC; k0 += 16) {
        // load A tile (coalesced float4, conflict-free stores)
        *(float4*)&As[ka][oa]     = *(const float4*)&g_WpT[(k0 + ka) * OO + o0 + oa];
        *(float4*)&As[ka + 8][oa] = *(const float4*)&g_WpT[(k0 + ka + 8) * OO + o0 + oa];

        // load B tile: on-the-fly temporal shift of x (2 coalesced taps)
#pragma unroll
        for (int p = 0; p < 4; ++p) {
            int cl = cb0 + p * 4;
            int c  = k0 + cl;
            const float* row = xn + (size_t)c * TV;
            int   i0 = g_idx_in[c * TT + tb];
            float fr = g_frac_in[c * TT + tb];
            float v1 = (i0 >= 0 && i0 < TT)      ? row[i0 * 25 + vb]      : 0.f;
            float v2 = (i0 >= -1 && i0 < TT - 1) ? row[i0 * 25 + 25 + vb] : 0.f;
            Bs[cl][jb] = v1 + fr * (v2 - v1);
        }
        __syncthreads();

#pragma unroll
        for (int kk = 0; kk < 16; ++kk) {
            ulonglong2 a01 = *(const ulonglong2*)&As[kk][ty * 8];
            ulonglong2 a23 = *(const ulonglong2*)&As[kk][ty * 8 + 4];
            float4 b = *(const float4*)&Bs[kk][tx * 4];
            unsigned long long av[4] = { a01.x, a01.y, a23.x, a23.y };
            unsigned long long bv[4] = { pack2(b.x, b.x), pack2(b.y, b.y),
                                         pack2(b.z, b.z), pack2(b.w, b.w) };
#pragma unroll
            for (int m = 0; m < 4; ++m)
#pragma unroll
                for (int j = 0; j < 4; ++j)
                    fma2(acc[m][j], av[m], bv[j]);
        }
        __syncthreads();
    }

    // epilogue: + bias2[o][t], ReLU, write h2 (float4 stores)
    int tcol[4];
#pragma unroll
    for (int j = 0; j < 4; ++j) tcol[j] = (tv0 + tx * 4 + j) / 25;

#pragma unroll
    for (int m = 0; m < 4; ++m) {
        float2 c0 = unpack2(acc[m][0]);
        float2 c1 = unpack2(acc[m][1]);
        float2 c2 = unpack2(acc[m][2]);
        float2 c3 = unpack2(acc[m][3]);
        int oA = o0 + ty * 8 + 2 * m;   // .x lane
        int oB = oA + 1;                // .y lane
        float4 va, vb4;
        va.x  = fmaxf(c0.x + g_bias2[oA * TT + tcol[0]], 0.f);
        va.y  = fmaxf(c1.x + g_bias2[oA * TT + tcol[1]], 0.f);
        va.z  = fmaxf(c2.x + g_bias2[oA * TT + tcol[2]], 0.f);
        va.w  = fmaxf(c3.x + g_bias2[oA * TT + tcol[3]], 0.f);
        vb4.x = fmaxf(c0.y + g_bias2[oB * TT + tcol[0]], 0.f);
        vb4.y = fmaxf(c1.y + g_bias2[oB * TT + tcol[1]], 0.f);
        vb4.z = fmaxf(c2.y + g_bias2[oB * TT + tcol[2]], 0.f);
        vb4.w = fmaxf(c3.y + g_bias2[oB * TT + tcol[3]], 0.f);
        float* dA = g_h2 + ((size_t)(n * OO + oA)) * TV + tv0 + tx * 4;
        *(float4*)dA          = va;
        *(float4*)(dA + TV)   = vb4;
    }
}

// ---------------- kernel 6: BN2 stats over shift_out(h2) ---------------------
__global__ void stats2_kernel(const float* __restrict__ g2,
                              const float* __restrict__ b2) {
    const int o = blockIdx.x;
    float s = 0.f, ss = 0.f;
    for (int n = 0; n < NB; ++n) {
        const float* row = g_h2 + ((size_t)n * OO + o) * TV;
        for (int i = threadIdx.x; i < TV; i += 256) {
            int t = i / 25;
            int v = i - t * 25;
            int   i0 = g_idx_out[o * TT + t];
            float fr = g_frac_out[o * TT + t];
            float v1 = (i0 >= 0 && i0 < TT)      ? row[i0 * 25 + v]      : 0.f;
            float v2 = (i0 >= -1 && i0 < TT - 1) ? row[i0 * 25 + 25 + v] : 0.f;
            float sv = v1 + fr * (v2 - v1);
            s += sv; ss += sv * sv;
        }
    }
    __shared__ float sh1[256], sh2[256];
    sh1[threadIdx.x] = s; sh2[threadIdx.x] = ss;
    __syncthreads();
    for (int off = 128; off > 0; off >>= 1) {
        if (threadIdx.x < off) {
            sh1[threadIdx.x] += sh1[threadIdx.x + off];
            sh2[threadIdx.x] += sh2[threadIdx.x + off];
        }
        __syncthreads();
    }
    if (threadIdx.x == 0) {
        float mean = sh1[0] / (float)NTV;
        float var  = sh2[0] / (float)NTV - mean * mean;
        float a = g2[o] * rsqrtf(var + 1e-5f);
        g_A2[o] = a;
        g_D2[o] = b2[o] - mean * a;
    }
}

// ---------------- kernel 7: final shift_out + BN2 -> out ---------------------
__global__ void final_kernel(float* __restrict__ out) {
    const int b = blockIdx.x;        // b = n*256 + o
    const int o = b & 255;
    const float* row = g_h2 + (size_t)b * TV;
    float* orow = out + (size_t)b * TV;
    const float A = g_A2[o], D = g_D2[o];
    for (int i = threadIdx.x; i < TV; i += 256) {
        int t = i / 25;
        int v = i - t * 25;
        int   i0 = g_idx_out[o * TT + t];
        float fr = g_frac_out[o * TT + t];
        float v1 = (i0 >= 0 && i0 < TT)      ? row[i0 * 25 + v]      : 0.f;
        float v2 = (i0 >= -1 && i0 < TT - 1) ? row[i0 * 25 + 25 + v] : 0.f;
        float sv = v1 + fr * (v2 - v1);
        orow[i] = A * sv + D;
    }
}

// ---------------- launch ------------------------------------------------------
extern "C" void kernel_launch(void* const* d_in, const int* in_sizes, int n_in,
                              void* d_out, int out_size) {
    const float* x      = (const float*)d_in[0];
    const float* conv_w = (const float*)d_in[1];
    const float* conv_b = (const float*)d_in[2];
    const float* bn1_g  = (const float*)d_in[3];
    const float* bn1_b  = (const float*)d_in[4];
    const float* bn2_g  = (const float*)d_in[5];
    const float* bn2_b  = (const float*)d_in[6];
    const float* th_in  = (const float*)d_in[7];
    const float* th_out = (const float*)d_in[8];
    float* out = (float*)d_out;

    stats_x_kernel<<<CC, 256>>>(x, bn1_g, bn1_b);
    tables_kernel<<<(CC * TT + 255) / 256, 256>>>(th_in, th_out);
    wprep_kernel<<<OO, 256>>>(conv_w);
    bias_kernel<<<OO, 64>>>(conv_w, conv_b);
    gemm_kernel<<<dim3(TV / 64, OO / 128, NB), 256>>>(x);
    stats2_kernel<<<OO, 256>>>(bn2_g, bn2_b);
    final_kernel<<<NB * OO, 256>>>(out);
}

// round 5
// speedup vs baseline: 1.7176x; 1.7176x over previous
#include <cuda_runtime.h>
#include <cuda_bf16.h>

// Problem dims (fixed): N=64, C=Cin=256, O=Cout=256, T=64, V=25, TV=1600
#define NB   64
#define CC   256
#define OO   256
#define TT   64
#define VV   25
#define TV   1600
#define NTV  102400   // N*T*V elements per channel
#define NSPLIT 8

// ---------------- scratch (device globals; no cudaMalloc allowed) ------------
__device__ float g_h2[(size_t)NB * OO * TV];   // relu(conv) output, 104.9 MB
__device__ float g_WpT[CC * OO];               // W'[c][o] = w[o][c]*a_c (transposed)
__device__ float g_aC[CC], g_dC[CC];           // BN1 fold
__device__ float g_bias2[OO * TT];
__device__ int   g_idx_in[CC * TT];
__device__ float g_frac_in[CC * TT];
__device__ int   g_idx_out[OO * TT];
__device__ float g_frac_out[OO * TT];
__device__ float g_dm[CC * TT];                // d_c * mask(c,t)
__device__ float g_A2[OO], g_D2[OO];           // BN2 scale/shift
__device__ float g_part1[NSPLIT][2][CC];       // stage-1 partials for BN1 stats
__device__ float g_part2[NSPLIT][2][OO];       // stage-1 partials for BN2 stats

// ---------------- packed f32x2 helpers (Blackwell 2xFP32) --------------------
__device__ __forceinline__ void fma2(unsigned long long& d,
                                     unsigned long long a,
                                     unsigned long long b) {
    asm("fma.rn.f32x2 %0, %1, %2, %3;" : "=l"(d) : "l"(a), "l"(b), "l"(d));
}
__device__ __forceinline__ unsigned long long pack2(float lo, float hi) {
    unsigned long long r;
    asm("mov.b64 %0, {%1, %2};" : "=l"(r) : "f"(lo), "f"(hi));
    return r;
}
__device__ __forceinline__ float2 unpack2(unsigned long long v) {
    float2 r;
    asm("mov.b64 {%0, %1}, %2;" : "=f"(r.x), "=f"(r.y) : "l"(v));
    return r;
}

// ---------------- block reduce (256 threads, 2 values) -----------------------
__device__ __forceinline__ void block_reduce2(float& s, float& ss) {
    __shared__ float sh1[256], sh2[256];
    sh1[threadIdx.x] = s; sh2[threadIdx.x] = ss;
    __syncthreads();
    for (int off = 128; off > 0; off >>= 1) {
        if (threadIdx.x < off) {
            sh1[threadIdx.x] += sh1[threadIdx.x + off];
            sh2[threadIdx.x] += sh2[threadIdx.x + off];
        }
        __syncthreads();
    }
    s = sh1[0]; ss = sh2[0];
}

// ---------------- kernel 1a: x stats, stage 1 (grid CC x NSPLIT) -------------
__global__ void stats_x_kernel(const float* __restrict__ x) {
    const int c = blockIdx.x, nb = blockIdx.y;
    float s = 0.f, ss = 0.f;
    for (int n = nb * (NB / NSPLIT); n < (nb + 1) * (NB / NSPLIT); ++n) {
        const float4* row = (const float4*)(x + ((size_t)n * CC + c) * TV);
        for (int i = threadIdx.x; i < TV / 4; i += 256) {
            float4 v = row[i];
            s  += v.x + v.y + v.z + v.w;
            ss += v.x * v.x + v.y * v.y + v.z * v.z + v.w * v.w;
        }
    }
    block_reduce2(s, ss);
    if (threadIdx.x == 0) { g_part1[nb][0][c] = s; g_part1[nb][1][c] = ss; }
}

// ---------------- kernel 1b: BN1 finalize -------------------------------------
__global__ void bn1_finalize(const float* __restrict__ g1,
                             const float* __restrict__ b1) {
    int c = threadIdx.x;
    float s = 0.f, ss = 0.f;
    for (int nb = 0; nb < NSPLIT; ++nb) { s += g_part1[nb][0][c]; ss += g_part1[nb][1][c]; }
    float mean = s / (float)NTV;
    float var  = ss / (float)NTV - mean * mean;
    float a = g1[c] * rsqrtf(var + 1e-5f);
    g_aC[c] = a;
    g_dC[c] = b1[c] - mean * a;
}

// ---------------- kernel 2: shift tables (exact JAX floor semantics) ---------
__global__ void tables_kernel(const float* __restrict__ th_in,
                              const float* __restrict__ th_out) {
    int gid = blockIdx.x * blockDim.x + threadIdx.x;
    if (gid >= CC * TT) return;
    int c = gid >> 6, t = gid & 63;
    {
        float pos = (float)t + th_in[c];
        float fl = floorf(pos);
        int i0 = (int)fl;
        float fr = pos - fl;
        g_idx_in[gid] = i0;
        g_frac_in[gid] = fr;
        float m = ((i0 >= 0 && i0 < TT) ? (1.f - fr) : 0.f)
                + ((i0 + 1 >= 0 && i0 + 1 < TT) ? fr : 0.f);
        g_dm[gid] = g_dC[c] * m;
    }
    {
        float pos = (float)t + th_out[c];
        float fl = floorf(pos);
        int i0 = (int)fl;
        float fr = pos - fl;
        g_idx_out[gid] = i0;
        g_frac_out[gid] = fr;
    }
}

// ---------------- kernel 3: W' transposed with BN1 scale folded --------------
__global__ void wprep_kernel(const float* __restrict__ w) {
    int o = blockIdx.x, c = threadIdx.x;
    g_WpT[c * OO + o] = w[o * CC + c] * g_aC[c];
}

// ---------------- kernel 4: bias2[o][t] = conv_b + sum_c w*d_c*m(c,t) --------
__global__ void bias_kernel(const float* __restrict__ w,
                            const float* __restrict__ cb) {
    const int o = blockIdx.x;
    const int t = threadIdx.x & 63;
    const int cg = threadIdx.x >> 6;          // 4 c-chunks of 64
    float s = 0.f;
#pragma unroll 4
    for (int c = cg * 64; c < cg * 64 + 64; ++c)
        s += w[o * CC + c] * g_dm[c * TT + t];
    __shared__ float sh[256];
    sh[threadIdx.x] = s;
    __syncthreads();
    if (cg == 0)
        g_bias2[o * TT + t] = cb[o] + sh[t] + sh[64 + t] + sh[128 + t] + sh[192 + t];
}

// ---------------- kernel 5: fused shift_in + GEMM + bias + ReLU --------------
// Tile: 256(O) x 64(TV) x 16(K). 256 threads, 8x8 per-thread, f32x2 FMA.
// h2[n,o,tv] = relu( sum_c W'[o,c] * sx[n,c,tv] + bias2[o, t(tv)] )
__global__ void __launch_bounds__(256, 2)
gemm_kernel(const float* __restrict__ x) {
    __shared__ float As[16][256];  // A[k][o]
    __shared__ float Bs[16][64];   // B[k][j]

    const int tid = threadIdx.x;
    const int n   = blockIdx.z;
    const int tv0 = blockIdx.x * 64;

    // B loader coords (one column, 4 K-rows per tile)
    const int jb  = tid & 63;
    const int cb0 = tid >> 6;                 // 0..3
    const int tvb = tv0 + jb;
    const int tb  = tvb / 25;
    const int vb  = tvb - tb * 25;
    const float* xn = x + (size_t)n * CC * TV;

    // compute mapping: 8x8 per thread
    const int tx = tid & 7;    // TV group
    const int ty = tid >> 3;   // O group (0..31)

    unsigned long long acc[4][8];
#pragma unroll
    for (int m = 0; m < 4; ++m)
#pragma unroll
        for (int j = 0; j < 8; ++j) acc[m][j] = 0ull;

    float4 aReg[4];
    float  bReg[4];

    // prologue: prefetch tile 0
#pragma unroll
    for (int p = 0; p < 4; ++p) {
        int e = p * 1024 + tid * 4;
        aReg[p] = *(const float4*)&g_WpT[(e >> 8) * OO + (e & 255)];
    }
#pragma unroll
    for (int p = 0; p < 4; ++p) {
        int c = cb0 + p * 4;
        const float* row = xn + (size_t)c * TV;
        int   i0 = g_idx_in[c * TT + tb];
        float fr = g_frac_in[c * TT + tb];
        float v1 = (i0 >= 0 && i0 < TT)      ? row[i0 * 25 + vb]      : 0.f;
        float v2 = (i0 >= -1 && i0 < TT - 1) ? row[i0 * 25 + 25 + vb] : 0.f;
        bReg[p] = v1 + fr * (v2 - v1);
    }

    for (int k0 = 0; k0 < CC; k0 += 16) {
        // stage prefetched tile into smem
#pragma unroll
        for (int p = 0; p < 4; ++p) {
            int e = p * 1024 + tid * 4;
            *(float4*)&As[e >> 8][e & 255] = aReg[p];
        }
#pragma unroll
        for (int p = 0; p < 4; ++p) Bs[cb0 + p * 4][jb] = bReg[p];
        __syncthreads();

        // prefetch next tile (global loads overlap compute)
        if (k0 + 16 < CC) {
#pragma unroll
            for (int p = 0; p < 4; ++p) {
                int e = p * 1024 + tid * 4;
                aReg[p] = *(const float4*)&g_WpT[(k0 + 16 + (e >> 8)) * OO + (e & 255)];
            }
#pragma unroll
            for (int p = 0; p < 4; ++p) {
                int c = k0 + 16 + cb0 + p * 4;
                const float* row = xn + (size_t)c * TV;
                int   i0 = g_idx_in[c * TT + tb];
                float fr = g_frac_in[c * TT + tb];
                float v1 = (i0 >= 0 && i0 < TT)      ? row[i0 * 25 + vb]      : 0.f;
                float v2 = (i0 >= -1 && i0 < TT - 1) ? row[i0 * 25 + 25 + vb] : 0.f;
                bReg[p] = v1 + fr * (v2 - v1);
            }
        }

#pragma unroll
        for (int kk = 0; kk < 16; ++kk) {
            ulonglong2 a01 = *(const ulonglong2*)&As[kk][ty * 8];
            ulonglong2 a23 = *(const ulonglong2*)&As[kk][ty * 8 + 4];
            float4 b0 = *(const float4*)&Bs[kk][tx * 8];
            float4 b1 = *(const float4*)&Bs[kk][tx * 8 + 4];
            unsigned long long av[4] = { a01.x, a01.y, a23.x, a23.y };
            unsigned long long bv[8] = {
                pack2(b0.x, b0.x), pack2(b0.y, b0.y), pack2(b0.z, b0.z), pack2(b0.w, b0.w),
                pack2(b1.x, b1.x), pack2(b1.y, b1.y), pack2(b1.z, b1.z), pack2(b1.w, b1.w) };
#pragma unroll
            for (int m = 0; m < 4; ++m)
#pragma unroll
                for (int j = 0; j < 8; ++j)
                    fma2(acc[m][j], av[m], bv[j]);
        }
        __syncthreads();
    }

    // epilogue: + bias2[o][t], ReLU, write h2 (float4 stores)
    int tcol[8];
#pragma unroll
    for (int j = 0; j < 8; ++j) tcol[j] = (tv0 + tx * 8 + j) / 25;

#pragma unroll
    for (int m = 0; m < 4; ++m) {
        float2 c[8];
#pragma unroll
        for (int j = 0; j < 8; ++j) c[j] = unpack2(acc[m][j]);
        const int oA = ty * 8 + 2 * m;
        const int oB = oA + 1;
        const float* bA = &g_bias2[oA * TT];
        const float* bB = &g_bias2[oB * TT];
        float4 a0, a1, q0, q1;
        a0.x = fmaxf(c[0].x + bA[tcol[0]], 0.f);
        a0.y = fmaxf(c[1].x + bA[tcol[1]], 0.f);
        a0.z = fmaxf(c[2].x + bA[tcol[2]], 0.f);
        a0.w = fmaxf(c[3].x + bA[tcol[3]], 0.f);
        a1.x = fmaxf(c[4].x + bA[tcol[4]], 0.f);
        a1.y = fmaxf(c[5].x + bA[tcol[5]], 0.f);
        a1.z = fmaxf(c[6].x + bA[tcol[6]], 0.f);
        a1.w = fmaxf(c[7].x + bA[tcol[7]], 0.f);
        q0.x = fmaxf(c[0].y + bB[tcol[0]], 0.f);
        q0.y = fmaxf(c[1].y + bB[tcol[1]], 0.f);
        q0.z = fmaxf(c[2].y + bB[tcol[2]], 0.f);
        q0.w = fmaxf(c[3].y + bB[tcol[3]], 0.f);
        q1.x = fmaxf(c[4].y + bB[tcol[4]], 0.f);
        q1.y = fmaxf(c[5].y + bB[tcol[5]], 0.f);
        q1.z = fmaxf(c[6].y + bB[tcol[6]], 0.f);
        q1.w = fmaxf(c[7].y + bB[tcol[7]], 0.f);
        float* dA = g_h2 + ((size_t)(n * OO + oA)) * TV + tv0 + tx * 8;
        *(float4*)dA            = a0;
        *(float4*)(dA + 4)      = a1;
        *(float4*)(dA + TV)     = q0;
        *(float4*)(dA + TV + 4) = q1;
    }
}

// ---------------- kernel 6a: BN2 stats over shift_out(h2), stage 1 -----------
__global__ void stats2_kernel() {
    const int o = blockIdx.x, nb = blockIdx.y;
    __shared__ int   sIdx[TT];
    __shared__ float sFrac[TT];
    if (threadIdx.x < TT) {
        sIdx[threadIdx.x]  = g_idx_out[o * TT + threadIdx.x];
        sFrac[threadIdx.x] = g_frac_out[o * TT + threadIdx.x];
    }
    __syncthreads();
    float s = 0.f, ss = 0.f;
    for (int n = nb * (NB / NSPLIT); n < (nb + 1) * (NB / NSPLIT); ++n) {
        const float* row = g_h2 + ((size_t)n * OO + o) * TV;
        for (int i = threadIdx.x; i < TV; i += 256) {
            int t = i / 25;
            int v = i - t * 25;
            int   i0 = sIdx[t];
            float fr = sFrac[t];
            float v1 = (i0 >= 0 && i0 < TT)      ? row[i0 * 25 + v]      : 0.f;
            float v2 = (i0 >= -1 && i0 < TT - 1) ? row[i0 * 25 + 25 + v] : 0.f;
            float sv = v1 + fr * (v2 - v1);
            s += sv; ss += sv * sv;
        }
    }
    block_reduce2(s, ss);
    if (threadIdx.x == 0) { g_part2[nb][0][o] = s; g_part2[nb][1][o] = ss; }
}

// ---------------- kernel 6b: BN2 finalize -------------------------------------
__global__ void bn2_finalize(const float* __restrict__ g2,
                             const float* __restrict__ b2) {
    int o = threadIdx.x;
    float s = 0.f, ss = 0.f;
    for (int nb = 0; nb < NSPLIT; ++nb) { s += g_part2[nb][0][o]; ss += g_part2[nb][1][o]; }
    float mean = s / (float)NTV;
    float var  = ss / (float)NTV - mean * mean;
    float a = g2[o] * rsqrtf(var + 1e-5f);
    g_A2[o] = a;
    g_D2[o] = b2[o] - mean * a;
}

// ---------------- kernel 7: final shift_out + BN2 -> out ---------------------
__global__ void final_kernel(float* __restrict__ out) {
    const int b = blockIdx.x;        // b = n*256 + o
    const int o = b & 255;
    __shared__ int   sIdx[TT];
    __shared__ float sFrac[TT];
    if (threadIdx.x < TT) {
        sIdx[threadIdx.x]  = g_idx_out[o * TT + threadIdx.x];
        sFrac[threadIdx.x] = g_frac_out[o * TT + threadIdx.x];
    }
    __syncthreads();
    const float* row = g_h2 + (size_t)b * TV;
    float* orow = out + (size_t)b * TV;
    const float A = g_A2[o], D = g_D2[o];
    for (int i = threadIdx.x; i < TV; i += 256) {
        int t = i / 25;
        int v = i - t * 25;
        int   i0 = sIdx[t];
        float fr = sFrac[t];
        float v1 = (i0 >= 0 && i0 < TT)      ? row[i0 * 25 + v]      : 0.f;
        float v2 = (i0 >= -1 && i0 < TT - 1) ? row[i0 * 25 + 25 + v] : 0.f;
        float sv = v1 + fr * (v2 - v1);
        orow[i] = A * sv + D;
    }
}

// ---------------- launch ------------------------------------------------------
extern "C" void kernel_launch(void* const* d_in, const int* in_sizes, int n_in,
                              void* d_out, int out_size) {
    const float* x      = (const float*)d_in[0];
    const float* conv_w = (const float*)d_in[1];
    const float* conv_b = (const float*)d_in[2];
    const float* bn1_g  = (const float*)d_in[3];
    const float* bn1_b  = (const float*)d_in[4];
    const float* bn2_g  = (const float*)d_in[5];
    const float* bn2_b  = (const float*)d_in[6];
    const float* th_in  = (const float*)d_in[7];
    const float* th_out = (const float*)d_in[8];
    float* out = (float*)d_out;

    stats_x_kernel<<<dim3(CC, NSPLIT), 256>>>(x);
    bn1_finalize<<<1, 256>>>(bn1_g, bn1_b);
    tables_kernel<<<(CC * TT + 255) / 256, 256>>>(th_in, th_out);
    wprep_kernel<<<OO, 256>>>(conv_w);
    bias_kernel<<<OO, 256>>>(conv_w, conv_b);
    gemm_kernel<<<dim3(TV / 64, 1, NB), 256>>>(x);
    stats2_kernel<<<dim3(OO, NSPLIT), 256>>>();
    bn2_finalize<<<1, 256>>>(bn2_g, bn2_b);
    final_kernel<<<NB * OO, 256>>>(out);
}

// round 12
// speedup vs baseline: 1.8357x; 1.0687x over previous
#include <cuda_runtime.h>
#include <cuda_bf16.h>
#include <cstdint>

// Problem dims (fixed): N=64, C=Cin=256, O=Cout=256, T=64, V=25, TV=1600
#define NB   64
#define CC   256
#define OO   256
#define TT   64
#define VV   25
#define TV   1600
#define NTV  102400
#define NSPLIT 8

// ---------------- scratch (device globals) -----------------------------------
__device__ float g_h2[(size_t)NB * OO * TV];       // relu(conv) output
__device__ __nv_bfloat16 g_Whi[OO * CC];           // W' bf16 high part [o][c]
__device__ __nv_bfloat16 g_Wlo[OO * CC];           // W' bf16 low  part [o][c]
__device__ float g_aC[CC], g_dC[CC];
__device__ float g_bias2[OO * TT];
__device__ int   g_idx_in[CC * TT];
__device__ float g_frac_in[CC * TT];
__device__ int   g_idx_out[OO * TT];
__device__ float g_frac_out[OO * TT];
__device__ float g_dm[CC * TT];
__device__ float g_A2[OO], g_D2[OO];
__device__ float g_part1[NSPLIT][2][CC];
__device__ float g_part2[NSPLIT][2][OO];

// ---------------- warp-MMA helpers (base-target PTX only) --------------------
__device__ __forceinline__ uint32_t smem_u32(const void* p) {
    uint32_t a;
    asm("{ .reg .u64 t; cvta.to.shared.u64 t, %1; cvt.u32.u64 %0, t; }"
        : "=r"(a) : "l"(p));
    return a;
}
#define LDSM4(r0, r1, r2, r3, addr) \
    asm volatile("ldmatrix.sync.aligned.m8n8.x4.shared.b16 {%0,%1,%2,%3}, [%4];" \
        : "=r"(r0), "=r"(r1), "=r"(r2), "=r"(r3) : "r"(addr))
#define MMA16816(d, a0, a1, a2, a3, b0, b1) \
    asm volatile("mma.sync.aligned.m16n8k16.row.col.f32.bf16.bf16.f32 " \
        "{%0,%1,%2,%3}, {%4,%5,%6,%7}, {%8,%9}, {%0,%1,%2,%3};" \
        : "+f"((d)[0]), "+f"((d)[1]), "+f"((d)[2]), "+f"((d)[3]) \
        : "r"(a0), "r"(a1), "r"(a2), "r"(a3), "r"(b0), "r"(b1))

// ---------------- block reduce -------------------------------------------------
__device__ __forceinline__ void block_reduce2(float& s, float& ss) {
    __shared__ float sh1[256], sh2[256];
    sh1[threadIdx.x] = s; sh2[threadIdx.x] = ss;
    __syncthreads();
    for (int off = 128; off > 0; off >>= 1) {
        if (threadIdx.x < off) {
            sh1[threadIdx.x] += sh1[threadIdx.x + off];
            sh2[threadIdx.x] += sh2[threadIdx.x + off];
        }
        __syncthreads();
    }
    s = sh1[0]; ss = sh2[0];
}

// ---------------- kernel 1a/1b: BN1 stats --------------------------------------
__global__ void stats_x_kernel(const float* __restrict__ x) {
    const int c = blockIdx.x, nb = blockIdx.y;
    float s = 0.f, ss = 0.f;
    for (int n = nb * (NB / NSPLIT); n < (nb + 1) * (NB / NSPLIT); ++n) {
        const float4* row = (const float4*)(x + ((size_t)n * CC + c) * TV);
        for (int i = threadIdx.x; i < TV / 4; i += 256) {
            float4 v = row[i];
            s  += v.x + v.y + v.z + v.w;
            ss += v.x * v.x + v.y * v.y + v.z * v.z + v.w * v.w;
        }
    }
    block_reduce2(s, ss);
    if (threadIdx.x == 0) { g_part1[nb][0][c] = s; g_part1[nb][1][c] = ss; }
}
__global__ void bn1_finalize(const float* __restrict__ g1,
                             const float* __restrict__ b1) {
    int c = threadIdx.x;
    float s = 0.f, ss = 0.f;
    for (int nb = 0; nb < NSPLIT; ++nb) { s += g_part1[nb][0][c]; ss += g_part1[nb][1][c]; }
    float mean = s / (float)NTV;
    float var  = ss / (float)NTV - mean * mean;
    float a = g1[c] * rsqrtf(var + 1e-5f);
    g_aC[c] = a;
    g_dC[c] = b1[c] - mean * a;
}

// ---------------- kernel 2: shift tables ---------------------------------------
__global__ void tables_kernel(const float* __restrict__ th_in,
                              const float* __restrict__ th_out) {
    int gid = blockIdx.x * blockDim.x + threadIdx.x;
    if (gid >= CC * TT) return;
    int c = gid >> 6, t = gid & 63;
    {
        float pos = (float)t + th_in[c];
        float fl = floorf(pos);
        int i0 = (int)fl;
        float fr = pos - fl;
        g_idx_in[gid] = i0;
        g_frac_in[gid] = fr;
        float m = ((i0 >= 0 && i0 < TT) ? (1.f - fr) : 0.f)
                + ((i0 + 1 >= 0 && i0 + 1 < TT) ? fr : 0.f);
        g_dm[gid] = g_dC[c] * m;
    }
    {
        float pos = (float)t + th_out[c];
        float fl = floorf(pos);
        int i0 = (int)fl;
        float fr = pos - fl;
        g_idx_out[gid] = i0;
        g_frac_out[gid] = fr;
    }
}

// ---------------- kernel 3: W' -> bf16 hi/lo ------------------------------------
__global__ void wprep_kernel(const float* __restrict__ w) {
    int o = blockIdx.x, c = threadIdx.x;
    float wp = w[o * CC + c] * g_aC[c];
    __nv_bfloat16 hi = __float2bfloat16(wp);
    __nv_bfloat16 lo = __float2bfloat16(wp - __bfloat162float(hi));
    g_Whi[o * CC + c] = hi;
    g_Wlo[o * CC + c] = lo;
}

// ---------------- kernel 4: bias2 ----------------------------------------------
__global__ void bias_kernel(const float* __restrict__ w,
                            const float* __restrict__ cb) {
    const int o = blockIdx.x;
    const int t = threadIdx.x & 63;
    const int cg = threadIdx.x >> 6;
    float s = 0.f;
#pragma unroll 4
    for (int c = cg * 64; c < cg * 64 + 64; ++c)
        s += w[o * CC + c] * g_dm[c * TT + t];
    __shared__ float sh[256];
    sh[threadIdx.x] = s;
    __syncthreads();
    if (cg == 0)
        g_bias2[o * TT + t] = cb[o] + sh[t] + sh[64 + t] + sh[128 + t] + sh[192 + t];
}

// ---------------- kernel 5: warp-MMA GEMM (shift_in fused, bf16 hi/lo) ----------
// Block: M=128(O) x N=64(tv) x K=256 resident; loops over 8 n-images.
// 8 warps; warp tile 64x16; mma.m16n8k16 bf16, fp32 accum, 3 split terms.
#define KW 132                               // padded uint32 words per K-row
#define SM_A_HI  0
#define SM_A_LO  (SM_A_HI + 128 * KW * 4)    // 67584
#define SM_B_HI  (SM_A_LO + 128 * KW * 4)    // 135168
#define SM_B_LO  (SM_B_HI + 64 * KW * 4)     // 168960
#define SM_TIDX  (SM_B_LO + 64 * KW * 4)     // 202752
#define SM_TFRC  (SM_TIDX + 4096)            // 206848
#define SM_TOTAL (SM_TFRC + 4096)            // 210944

__global__ void __launch_bounds__(256, 1)
gemm_mma(const float* __restrict__ x) {
    extern __shared__ char smem[];
    const uint32_t sb = smem_u32(smem);
    uint32_t* Ahi32 = (uint32_t*)(smem + SM_A_HI);
    uint32_t* Alo32 = (uint32_t*)(smem + SM_A_LO);
    uint32_t* Bhi32 = (uint32_t*)(smem + SM_B_HI);
    uint32_t* Blo32 = (uint32_t*)(smem + SM_B_LO);
    int*   sIdx = (int*)(smem + SM_TIDX);     // [4][256]
    float* sFrc = (float*)(smem + SM_TFRC);   // [4][256]

    const int tid  = threadIdx.x;
    const int w    = tid >> 5;
    const int lane = tid & 31;
    const int tv0  = blockIdx.x * 64;
    const int o0   = blockIdx.y * 128;
    const int n0   = blockIdx.z * (NB / 8);
    const int tmin = tv0 / 25;

    // ---- A fill (once): W' hi/lo, [128 rows m][256 cols k] padded ----
    {
        const uint4* srcHi = (const uint4*)(g_Whi + (size_t)o0 * CC);
        const uint4* srcLo = (const uint4*)(g_Wlo + (size_t)o0 * CC);
        for (int e = tid; e < 4096; e += 256) {
            int row = e >> 5, col8 = e & 31;
            int wi = row * KW + col8 * 4;
            *(uint4*)&Ahi32[wi] = srcHi[e];
            *(uint4*)&Alo32[wi] = srcLo[e];
        }
    }
    // ---- shift idx/frac cache: <=4 distinct t per tv-tile ----
    for (int e = tid; e < 1024; e += 256) {
        int t4 = e >> 8, c = e & 255;
        int t = tmin + t4; if (t > 63) t = 63;
        sIdx[t4 * 256 + c] = g_idx_in[c * TT + t];
        sFrc[t4 * 256 + c] = g_frac_in[c * TT + t];
    }
    __syncthreads();   // REQUIRED: sIdx/sFrc (and A) visible to all warps
                       // before any B-fill reads them (round-7 bug).

    // B-fill coords
    const int jb   = tid & 63;
    const int cblk = tid >> 6;               // 0..3
    const int tvb  = tv0 + jb;
    const int tb   = tvb / 25;
    const int vb   = tvb - tb * 25;
    const int tq   = tb - tmin;

    // warp tile coords
    const int m_warp = (w & 1) * 64;
    const int n_warp = (w >> 1) * 16;
    const int g   = lane >> 2;
    const int tig = lane & 3;
    // ldmatrix address components
    const int rowA   = (lane & 7) + ((lane >> 3) & 1) * 8;
    const int khalfA = lane >> 4;
    const int rowB   = (lane & 7) + ((lane >> 4) ? 8 : 0);
    const int khalfB = (lane >> 3) & 1;

    const uint32_t aHiB = sb + SM_A_HI, aLoB = sb + SM_A_LO;
    const uint32_t bHiB = sb + SM_B_HI, bLoB = sb + SM_B_LO;

    for (int it = 0; it < NB / 8; ++it) {
        const int n = n0 + it;
        const float* xn = x + (size_t)n * CC * TV;

        // ---- B fill: shifted x -> bf16 hi/lo, [64 rows j][256 cols c] ----
#pragma unroll
        for (int c8 = 0; c8 < 8; ++c8) {
            const int cbase = cblk * 64 + c8 * 8;
            uint32_t hp[4], lp[4];
#pragma unroll
            for (int p = 0; p < 4; ++p) {
                float v[2];
#pragma unroll
                for (int u = 0; u < 2; ++u) {
                    int c = cbase + p * 2 + u;
                    int   i0 = sIdx[tq * 256 + c];
                    float fr = sFrc[tq * 256 + c];
                    const float* row = xn + (size_t)c * TV;
                    float v1 = (i0 >= 0 && i0 < TT)      ? row[i0 * 25 + vb]      : 0.f;
                    float v2 = (i0 >= -1 && i0 < TT - 1) ? row[i0 * 25 + 25 + vb] : 0.f;
                    v[u] = v1 + fr * (v2 - v1);
                }
                __nv_bfloat16 h0 = __float2bfloat16(v[0]);
                __nv_bfloat16 h1 = __float2bfloat16(v[1]);
                __nv_bfloat16 l0 = __float2bfloat16(v[0] - __bfloat162float(h0));
                __nv_bfloat16 l1 = __float2bfloat16(v[1] - __bfloat162float(h1));
                hp[p] = ((uint32_t)__bfloat16_as_ushort(h1) << 16) | __bfloat16_as_ushort(h0);
                lp[p] = ((uint32_t)__bfloat16_as_ushort(l1) << 16) | __bfloat16_as_ushort(l0);
            }
            int wi = jb * KW + (cbase >> 1);
            *(uint4*)&Bhi32[wi] = *(uint4*)hp;
            *(uint4*)&Blo32[wi] = *(uint4*)lp;
        }
        __syncthreads();

        // ---- MMA mainloop: 16 k-steps x (4 mf x 2 nf x 3 terms) ----
        float acc[4][2][4];
#pragma unroll
        for (int mf = 0; mf < 4; ++mf)
#pragma unroll
            for (int nf = 0; nf < 2; ++nf)
#pragma unroll
                for (int q = 0; q < 4; ++q) acc[mf][nf][q] = 0.f;

#pragma unroll
        for (int ks = 0; ks < 16; ++ks) {
            const uint32_t kOff = (uint32_t)(ks * 8) * 4u;
            uint32_t bAddrOff = (uint32_t)((n_warp + rowB) * KW + khalfB * 4) * 4u + kOff;
            uint32_t bh[4], bl[4];
            LDSM4(bh[0], bh[1], bh[2], bh[3], bHiB + bAddrOff);
            LDSM4(bl[0], bl[1], bl[2], bl[3], bLoB + bAddrOff);
#pragma unroll
            for (int mf = 0; mf < 4; ++mf) {
                uint32_t aOff = (uint32_t)((m_warp + mf * 16 + rowA) * KW + khalfA * 4) * 4u + kOff;
                uint32_t ah[4], al[4];
                LDSM4(ah[0], ah[1], ah[2], ah[3], aHiB + aOff);
                LDSM4(al[0], al[1], al[2], al[3], aLoB + aOff);
#pragma unroll
                for (int nf = 0; nf < 2; ++nf) {
                    MMA16816(acc[mf][nf], ah[0], ah[1], ah[2], ah[3], bh[2 * nf], bh[2 * nf + 1]);
                    MMA16816(acc[mf][nf], ah[0], ah[1], ah[2], ah[3], bl[2 * nf], bl[2 * nf + 1]);
                    MMA16816(acc[mf][nf], al[0], al[1], al[2], al[3], bh[2 * nf], bh[2 * nf + 1]);
                }
            }
        }
        __syncthreads();   // all warps done reading B before next fill

        // ---- epilogue: bias + ReLU -> g_h2 ----
#pragma unroll
        for (int mf = 0; mf < 4; ++mf) {
            const int oA = o0 + m_warp + mf * 16 + g;
            const int oB = oA + 8;
            const float* btA = g_bias2 + (oA)*TT;
            const float* btB = g_bias2 + (oB)*TT;
            float* dA = g_h2 + ((size_t)(n * OO) + oA) * TV;
            float* dB = g_h2 + ((size_t)(n * OO) + oB) * TV;
#pragma unroll
            for (int nf = 0; nf < 2; ++nf) {
                const int col = tv0 + n_warp + nf * 8 + 2 * tig;
                const int t0 = col / 25, t1 = (col + 1) / 25;
                float2 v01, v23;
                v01.x = fmaxf(acc[mf][nf][0] + btA[t0], 0.f);
                v01.y = fmaxf(acc[mf][nf][1] + btA[t1], 0.f);
                v23.x = fmaxf(acc[mf][nf][2] + btB[t0], 0.f);
                v23.y = fmaxf(acc[mf][nf][3] + btB[t1], 0.f);
                *(float2*)(dA + col) = v01;
                *(float2*)(dB + col) = v23;
            }
        }
    }
}

// ---------------- kernel 6a/6b: BN2 stats over shift_out(h2) --------------------
__global__ void stats2_kernel() {
    const int o = blockIdx.x, nb = blockIdx.y;
    __shared__ int   sIdx[TT];
    __shared__ float sFrac[TT];
    if (threadIdx.x < TT) {
        sIdx[threadIdx.x]  = g_idx_out[o * TT + threadIdx.x];
        sFrac[threadIdx.x] = g_frac_out[o * TT + threadIdx.x];
    }
    __syncthreads();
    float s = 0.f, ss = 0.f;
    for (int n = nb * (NB / NSPLIT); n < (nb + 1) * (NB / NSPLIT); ++n) {
        const float* row = g_h2 + ((size_t)n * OO + o) * TV;
        for (int i = threadIdx.x; i < TV; i += 256) {
            int t = i / 25;
            int v = i - t * 25;
            int   i0 = sIdx[t];
            float fr = sFrac[t];
            float v1 = (i0 >= 0 && i0 < TT)      ? row[i0 * 25 + v]      : 0.f;
            float v2 = (i0 >= -1 && i0 < TT - 1) ? row[i0 * 25 + 25 + v] : 0.f;
            float sv = v1 + fr * (v2 - v1);
            s += sv; ss += sv * sv;
        }
    }
    block_reduce2(s, ss);
    if (threadIdx.x == 0) { g_part2[nb][0][o] = s; g_part2[nb][1][o] = ss; }
}
__global__ void bn2_finalize(const float* __restrict__ g2,
                             const float* __restrict__ b2) {
    int o = threadIdx.x;
    float s = 0.f, ss = 0.f;
    for (int nb = 0; nb < NSPLIT; ++nb) { s += g_part2[nb][0][o]; ss += g_part2[nb][1][o]; }
    float mean = s / (float)NTV;
    float var  = ss / (float)NTV - mean * mean;
    float a = g2[o] * rsqrtf(var + 1e-5f);
    g_A2[o] = a;
    g_D2[o] = b2[o] - mean * a;
}

// ---------------- kernel 7: final shift_out + BN2 -> out ------------------------
__global__ void final_kernel(float* __restrict__ out) {
    const int b = blockIdx.x;        // b = n*256 + o
    const int o = b & 255;
    __shared__ int   sIdx[TT];
    __shared__ float sFrac[TT];
    if (threadIdx.x < TT) {
        sIdx[threadIdx.x]  = g_idx_out[o * TT + threadIdx.x];
        sFrac[threadIdx.x] = g_frac_out[o * TT + threadIdx.x];
    }
    __syncthreads();
    const float* row = g_h2 + (size_t)b * TV;
    float* orow = out + (size_t)b * TV;
    const float A = g_A2[o], D = g_D2[o];
    for (int i = threadIdx.x; i < TV; i += 256) {
        int t = i / 25;
        int v = i - t * 25;
        int   i0 = sIdx[t];
        float fr = sFrac[t];
        float v1 = (i0 >= 0 && i0 < TT)      ? row[i0 * 25 + v]      : 0.f;
        float v2 = (i0 >= -1 && i0 < TT - 1) ? row[i0 * 25 + 25 + v] : 0.f;
        float sv = v1 + fr * (v2 - v1);
        orow[i] = A * sv + D;
    }
}

// ---------------- launch ---------------------------------------------------------
extern "C" void kernel_launch(void* const* d_in, const int* in_sizes, int n_in,
                              void* d_out, int out_size) {
    const float* x      = (const float*)d_in[0];
    const float* conv_w = (const float*)d_in[1];
    const float* conv_b = (const float*)d_in[2];
    const float* bn1_g  = (const float*)d_in[3];
    const float* bn1_b  = (const float*)d_in[4];
    const float* bn2_g  = (const float*)d_in[5];
    const float* bn2_b  = (const float*)d_in[6];
    const float* th_in  = (const float*)d_in[7];
    const float* th_out = (const float*)d_in[8];
    float* out = (float*)d_out;

    cudaFuncSetAttribute(gemm_mma, cudaFuncAttributeMaxDynamicSharedMemorySize, SM_TOTAL);

    stats_x_kernel<<<dim3(CC, NSPLIT), 256>>>(x);
    bn1_finalize<<<1, 256>>>(bn1_g, bn1_b);
    tables_kernel<<<(CC * TT + 255) / 256, 256>>>(th_in, th_out);
    wprep_kernel<<<OO, 256>>>(conv_w);
    bias_kernel<<<OO, 256>>>(conv_w, conv_b);
    gemm_mma<<<dim3(TV / 64, 2, NB / 8), 256, SM_TOTAL>>>(x);
    stats2_kernel<<<dim3(OO, NSPLIT), 256>>>();
    bn2_finalize<<<1, 256>>>(bn2_g, bn2_b);
    final_kernel<<<NB * OO, 256>>>(out);
}

// round 14
// speedup vs baseline: 2.0330x; 1.1075x over previous
#include <cuda_runtime.h>
#include <cuda_bf16.h>
#include <cstdint>

// Problem dims (fixed): N=64, C=Cin=256, O=Cout=256, T=64, V=25, TV=1600
#define NB   64
#define CC   256
#define OO   256
#define TT   64
#define VV   25
#define TV   1600
#define NTV  102400
#define NSPLIT 8

// ---------------- scratch (device globals) -----------------------------------
__device__ float g_h2[(size_t)NB * OO * TV];       // relu(conv) output
__device__ uint32_t g_Bhi[(size_t)NB * TV * 128];  // shifted x, bf16x2 hi, [n][tv][c/2]
__device__ uint32_t g_Blo[(size_t)NB * TV * 128];  // shifted x, bf16x2 lo
__device__ __nv_bfloat16 g_Whi[OO * CC];           // W' bf16 high part [o][c]
__device__ __nv_bfloat16 g_Wlo[OO * CC];           // W' bf16 low  part [o][c]
__device__ float g_aC[CC], g_dC[CC];
__device__ float g_bias2[OO * TT];
__device__ int   g_idx_in[CC * TT];
__device__ float g_frac_in[CC * TT];
__device__ int   g_idx_out[OO * TT];
__device__ float g_frac_out[OO * TT];
__device__ float g_dm[CC * TT];
__device__ float g_A2[OO], g_D2[OO];
__device__ float g_part1[NSPLIT][2][CC];
__device__ float g_part2[NSPLIT][2][OO];

// ---------------- warp-MMA / cp.async helpers (base-target PTX only) ----------
__device__ __forceinline__ uint32_t smem_u32(const void* p) {
    uint32_t a;
    asm("{ .reg .u64 t; cvta.to.shared.u64 t, %1; cvt.u32.u64 %0, t; }"
        : "=r"(a) : "l"(p));
    return a;
}
#define LDSM4(r0, r1, r2, r3, addr) \
    asm volatile("ldmatrix.sync.aligned.m8n8.x4.shared.b16 {%0,%1,%2,%3}, [%4];" \
        : "=r"(r0), "=r"(r1), "=r"(r2), "=r"(r3) : "r"(addr))
#define MMA16816(d, a0, a1, a2, a3, b0, b1) \
    asm volatile("mma.sync.aligned.m16n8k16.row.col.f32.bf16.bf16.f32 " \
        "{%0,%1,%2,%3}, {%4,%5,%6,%7}, {%8,%9}, {%0,%1,%2,%3};" \
        : "+f"((d)[0]), "+f"((d)[1]), "+f"((d)[2]), "+f"((d)[3]) \
        : "r"(a0), "r"(a1), "r"(a2), "r"(a3), "r"(b0), "r"(b1))
#define CP_ASYNC16(dst, src) \
    asm volatile("cp.async.cg.shared.global [%0], [%1], 16;" :: "r"(dst), "l"(src))
#define CP_COMMIT() asm volatile("cp.async.commit_group;" ::: "memory")
#define CP_WAIT1()  asm volatile("cp.async.wait_group 1;" ::: "memory")

// ---------------- block reduce -------------------------------------------------
__device__ __forceinline__ void block_reduce2(float& s, float& ss) {
    __shared__ float sh1[256], sh2[256];
    sh1[threadIdx.x] = s; sh2[threadIdx.x] = ss;
    __syncthreads();
    for (int off = 128; off > 0; off >>= 1) {
        if (threadIdx.x < off) {
            sh1[threadIdx.x] += sh1[threadIdx.x + off];
            sh2[threadIdx.x] += sh2[threadIdx.x + off];
        }
        __syncthreads();
    }
    s = sh1[0]; ss = sh2[0];
}

// ---------------- kernel 1a/1b: BN1 stats --------------------------------------
__global__ void stats_x_kernel(const float* __restrict__ x) {
    const int c = blockIdx.x, nb = blockIdx.y;
    float s = 0.f, ss = 0.f;
    for (int n = nb * (NB / NSPLIT); n < (nb + 1) * (NB / NSPLIT); ++n) {
        const float4* row = (const float4*)(x + ((size_t)n * CC + c) * TV);
        for (int i = threadIdx.x; i < TV / 4; i += 256) {
            float4 v = row[i];
            s  += v.x + v.y + v.z + v.w;
            ss += v.x * v.x + v.y * v.y + v.z * v.z + v.w * v.w;
        }
    }
    block_reduce2(s, ss);
    if (threadIdx.x == 0) { g_part1[nb][0][c] = s; g_part1[nb][1][c] = ss; }
}
__global__ void bn1_finalize(const float* __restrict__ g1,
                             const float* __restrict__ b1) {
    int c = threadIdx.x;
    float s = 0.f, ss = 0.f;
    for (int nb = 0; nb < NSPLIT; ++nb) { s += g_part1[nb][0][c]; ss += g_part1[nb][1][c]; }
    float mean = s / (float)NTV;
    float var  = ss / (float)NTV - mean * mean;
    float a = g1[c] * rsqrtf(var + 1e-5f);
    g_aC[c] = a;
    g_dC[c] = b1[c] - mean * a;
}

// ---------------- kernel 2: shift tables ---------------------------------------
__global__ void tables_kernel(const float* __restrict__ th_in,
                              const float* __restrict__ th_out) {
    int gid = blockIdx.x * blockDim.x + threadIdx.x;
    if (gid >= CC * TT) return;
    int c = gid >> 6, t = gid & 63;
    {
        float pos = (float)t + th_in[c];
        float fl = floorf(pos);
        int i0 = (int)fl;
        float fr = pos - fl;
        g_idx_in[gid] = i0;
        g_frac_in[gid] = fr;
        float m = ((i0 >= 0 && i0 < TT) ? (1.f - fr) : 0.f)
                + ((i0 + 1 >= 0 && i0 + 1 < TT) ? fr : 0.f);
        g_dm[gid] = g_dC[c] * m;
    }
    {
        float pos = (float)t + th_out[c];
        float fl = floorf(pos);
        int i0 = (int)fl;
        float fr = pos - fl;
        g_idx_out[gid] = i0;
        g_frac_out[gid] = fr;
    }
}

// ---------------- kernel 3: W' -> bf16 hi/lo ------------------------------------
__global__ void wprep_kernel(const float* __restrict__ w) {
    int o = blockIdx.x, c = threadIdx.x;
    float wp = w[o * CC + c] * g_aC[c];
    __nv_bfloat16 hi = __float2bfloat16(wp);
    __nv_bfloat16 lo = __float2bfloat16(wp - __bfloat162float(hi));
    g_Whi[o * CC + c] = hi;
    g_Wlo[o * CC + c] = lo;
}

// ---------------- kernel 4: bias2 ----------------------------------------------
__global__ void bias_kernel(const float* __restrict__ w,
                            const float* __restrict__ cb) {
    const int o = blockIdx.x;
    const int t = threadIdx.x & 63;
    const int cg = threadIdx.x >> 6;
    float s = 0.f;
#pragma unroll 4
    for (int c = cg * 64; c < cg * 64 + 64; ++c)
        s += w[o * CC + c] * g_dm[c * TT + t];
    __shared__ float sh[256];
    sh[threadIdx.x] = s;
    __syncthreads();
    if (cg == 0)
        g_bias2[o * TT + t] = cb[o] + sh[t] + sh[64 + t] + sh[128 + t] + sh[192 + t];
}

// ---------------- kernel 4b: bprep — shifted x -> bf16 hi/lo, [n][tv][c] --------
// grid (25 tv-tiles, NB n), 256 threads, dynamic smem staging (73 KB).
#define BP_HI   0
#define BP_LO   (64 * 132 * 4)
#define BP_IDX  (2 * 64 * 132 * 4)
#define BP_FRC  (BP_IDX + 4096)
#define BP_TOTAL (BP_FRC + 4096)

__global__ void __launch_bounds__(256, 1)
bprep_kernel(const float* __restrict__ x) {
    extern __shared__ char smem[];
    uint32_t* sHi = (uint32_t*)(smem + BP_HI);
    uint32_t* sLo = (uint32_t*)(smem + BP_LO);
    int*   sIdx = (int*)(smem + BP_IDX);
    float* sFrc = (float*)(smem + BP_FRC);

    const int tid = threadIdx.x;
    const int tv0 = blockIdx.x * 64;
    const int n   = blockIdx.y;
    const int tmin = tv0 / 25;

    for (int e = tid; e < 1024; e += 256) {
        int t4 = e >> 8, c = e & 255;
        int t = tmin + t4; if (t > 63) t = 63;
        sIdx[e] = g_idx_in[c * TT + t];
        sFrc[e] = g_frac_in[c * TT + t];
    }
    __syncthreads();

    const int jb   = tid & 63;
    const int cblk = tid >> 6;
    const int tvb  = tv0 + jb;
    const int tb   = tvb / 25;
    const int vb   = tvb - tb * 25;
    const int tq   = tb - tmin;
    const float* xn = x + (size_t)n * CC * TV;

#pragma unroll
    for (int c8 = 0; c8 < 8; ++c8) {
        const int cbase = cblk * 64 + c8 * 8;
        uint32_t hp[4], lp[4];
#pragma unroll
        for (int p = 0; p < 4; ++p) {
            float v[2];
#pragma unroll
            for (int u = 0; u < 2; ++u) {
                int c = cbase + p * 2 + u;
                int   i0 = sIdx[tq * 256 + c];
                float fr = sFrc[tq * 256 + c];
                const float* row = xn + (size_t)c * TV;
                float v1 = (i0 >= 0 && i0 < TT)      ? row[i0 * 25 + vb]      : 0.f;
                float v2 = (i0 >= -1 && i0 < TT - 1) ? row[i0 * 25 + 25 + vb] : 0.f;
                v[u] = v1 + fr * (v2 - v1);
            }
            __nv_bfloat16 h0 = __float2bfloat16(v[0]);
            __nv_bfloat16 h1 = __float2bfloat16(v[1]);
            __nv_bfloat16 l0 = __float2bfloat16(v[0] - __bfloat162float(h0));
            __nv_bfloat16 l1 = __float2bfloat16(v[1] - __bfloat162float(h1));
            hp[p] = ((uint32_t)__bfloat16_as_ushort(h1) << 16) | __bfloat16_as_ushort(h0);
            lp[p] = ((uint32_t)__bfloat16_as_ushort(l1) << 16) | __bfloat16_as_ushort(l0);
        }
        int wi = jb * 132 + (cbase >> 1);
        *(uint4*)&sHi[wi] = *(uint4*)hp;
        *(uint4*)&sLo[wi] = *(uint4*)lp;
    }
    __syncthreads();

    // coalesced write-out: [n][tv0+row][col], 128 u32 per row
    const size_t base = ((size_t)n * TV + tv0) * 128;
    for (int e = tid; e < 8192; e += 256) {
        int row = e >> 7, col = e & 127;
        g_Bhi[base + row * 128 + col] = sHi[row * 132 + col];
        g_Blo[base + row * 128 + col] = sLo[row * 132 + col];
    }
}

// ---------------- kernel 5: warp-MMA GEMM, cp.async double-buffered B -----------
// Block: M=128(O) x N=64(tv) x K=256; 8 n-images per CTA; K in 4 chunks of 64.
#define KW   132                             // A padded u32 words per m-row
#define BKW  36                              // B chunk padded u32 words per j-row
#define SM_A_HI  0
#define SM_A_LO  (SM_A_HI + 128 * KW * 4)    // 67584
#define SM_B     (SM_A_LO + 128 * KW * 4)    // 135168 ; 2 bufs x (hi 9216 + lo 9216)
#define SM_TOTAL (SM_B + 2 * 18432)          // 172032

__global__ void __launch_bounds__(256, 1)
gemm_mma(const float* __restrict__ x) {
    extern __shared__ char smem[];
    const uint32_t sb = smem_u32(smem);
    uint32_t* Ahi32 = (uint32_t*)(smem + SM_A_HI);
    uint32_t* Alo32 = (uint32_t*)(smem + SM_A_LO);

    const int tid  = threadIdx.x;
    const int w    = tid >> 5;
    const int lane = tid & 31;
    const int tv0  = blockIdx.x * 64;
    const int o0   = blockIdx.y * 128;
    const int n0   = blockIdx.z * (NB / 8);

    // ---- A fill (once): W' hi/lo, [128 m][256 k] padded ----
    {
        const uint4* srcHi = (const uint4*)(g_Whi + (size_t)o0 * CC);
        const uint4* srcLo = (const uint4*)(g_Wlo + (size_t)o0 * CC);
        for (int e = tid; e < 4096; e += 256) {
            int row = e >> 5, col8 = e & 31;
            int wi = row * KW + col8 * 4;
            *(uint4*)&Ahi32[wi] = srcHi[e];
            *(uint4*)&Alo32[wi] = srcLo[e];
        }
    }

    // chunk copier: (image nn, k-chunk kk) -> buffer buf
    auto copy_chunk = [&](int nn, int kk, int buf) {
        const uint32_t dH = sb + SM_B + buf * 18432;
        const uint32_t* srcH = g_Bhi + ((size_t)nn * TV + tv0) * 128 + kk * 32;
        const uint32_t* srcL = g_Blo + ((size_t)nn * TV + tv0) * 128 + kk * 32;
#pragma unroll
        for (int p = 0; p < 2; ++p) {
            int s = tid + p * 256;
            int row = s >> 3, sg = s & 7;
            uint32_t d = dH + (uint32_t)(row * BKW + sg * 4) * 4u;
            CP_ASYNC16(d,        (const void*)(srcH + row * 128 + sg * 4));
            CP_ASYNC16(d + 9216, (const void*)(srcL + row * 128 + sg * 4));
        }
    };

    // warp tile coords (identical to round-12 passing kernel)
    const int m_warp = (w & 1) * 64;
    const int n_warp = (w >> 1) * 16;
    const int g   = lane >> 2;
    const int tig = lane & 3;
    const int rowA   = (lane & 7) + ((lane >> 3) & 1) * 8;
    const int khalfA = lane >> 4;
    const int rowB   = (lane & 7) + ((lane >> 4) ? 8 : 0);
    const int khalfB = (lane >> 3) & 1;
    const uint32_t aHiB = sb + SM_A_HI, aLoB = sb + SM_A_LO;

    // prologue: prefetch first two chunks of image 0
    copy_chunk(n0, 0, 0); CP_COMMIT();
    copy_chunk(n0, 1, 1); CP_COMMIT();

    for (int it = 0; it < NB / 8; ++it) {
        const int n = n0 + it;
        float acc[4][2][4];
#pragma unroll
        for (int mf = 0; mf < 4; ++mf)
#pragma unroll
            for (int nf = 0; nf < 2; ++nf)
#pragma unroll
                for (int q = 0; q < 4; ++q) acc[mf][nf][q] = 0.f;

        for (int kc = 0; kc < 4; ++kc) {
            CP_WAIT1();
            __syncthreads();   // chunk kc visible to all warps; also covers A-fill

            const uint32_t bufH = sb + SM_B + (uint32_t)(kc & 1) * 18432;
#pragma unroll
            for (int ksl = 0; ksl < 4; ++ksl) {
                uint32_t bAddr = bufH
                    + (uint32_t)((n_warp + rowB) * BKW + khalfB * 4 + ksl * 8) * 4u;
                uint32_t bh[4], bl[4];
                LDSM4(bh[0], bh[1], bh[2], bh[3], bAddr);
                LDSM4(bl[0], bl[1], bl[2], bl[3], bAddr + 9216);
#pragma unroll
                for (int mf = 0; mf < 4; ++mf) {
                    uint32_t aOff = (uint32_t)((m_warp + mf * 16 + rowA) * KW
                                    + khalfA * 4 + kc * 32 + ksl * 8) * 4u;
                    uint32_t ah[4], al[4];
                    LDSM4(ah[0], ah[1], ah[2], ah[3], aHiB + aOff);
                    LDSM4(al[0], al[1], al[2], al[3], aLoB + aOff);
#pragma unroll
                    for (int nf = 0; nf < 2; ++nf) {
                        MMA16816(acc[mf][nf], ah[0], ah[1], ah[2], ah[3], bh[2*nf], bh[2*nf+1]);
                        MMA16816(acc[mf][nf], ah[0], ah[1], ah[2], ah[3], bl[2*nf], bl[2*nf+1]);
                        MMA16816(acc[mf][nf], al[0], al[1], al[2], al[3], bh[2*nf], bh[2*nf+1]);
                    }
                }
            }
            __syncthreads();   // all warps done reading buf before refilling it

            int g2 = it * 4 + kc + 2;   // global chunk index to prefetch
            if (g2 < 32) copy_chunk(n0 + (g2 >> 2), g2 & 3, kc & 1);
            CP_COMMIT();       // always commit (possibly empty) to keep counts aligned
        }

        // ---- epilogue: bias + ReLU -> g_h2 (overlaps with next prefetch) ----
#pragma unroll
        for (int mf = 0; mf < 4; ++mf) {
            const int oA = o0 + m_warp + mf * 16 + g;
            const int oB = oA + 8;
            const float* btA = g_bias2 + (oA)*TT;
            const float* btB = g_bias2 + (oB)*TT;
            float* dA = g_h2 + ((size_t)(n * OO) + oA) * TV;
            float* dB = g_h2 + ((size_t)(n * OO) + oB) * TV;
#pragma unroll
            for (int nf = 0; nf < 2; ++nf) {
                const int col = tv0 + n_warp + nf * 8 + 2 * tig;
                const int t0 = col / 25, t1 = (col + 1) / 25;
                float2 v01, v23;
                v01.x = fmaxf(acc[mf][nf][0] + btA[t0], 0.f);
                v01.y = fmaxf(acc[mf][nf][1] + btA[t1], 0.f);
                v23.x = fmaxf(acc[mf][nf][2] + btB[t0], 0.f);
                v23.y = fmaxf(acc[mf][nf][3] + btB[t1], 0.f);
                *(float2*)(dA + col) = v01;
                *(float2*)(dB + col) = v23;
            }
        }
    }
}

// ---------------- kernel 6a/6b: BN2 stats over shift_out(h2) --------------------
__global__ void stats2_kernel() {
    const int o = blockIdx.x, nb = blockIdx.y;
    __shared__ int   sIdx[TT];
    __shared__ float sFrac[TT];
    if (threadIdx.x < TT) {
        sIdx[threadIdx.x]  = g_idx_out[o * TT + threadIdx.x];
        sFrac[threadIdx.x] = g_frac_out[o * TT + threadIdx.x];
    }
    __syncthreads();
    float s = 0.f, ss = 0.f;
    for (int n = nb * (NB / NSPLIT); n < (nb + 1) * (NB / NSPLIT); ++n) {
        const float* row = g_h2 + ((size_t)n * OO + o) * TV;
        for (int i = threadIdx.x; i < TV; i += 256) {
            int t = i / 25;
            int v = i - t * 25;
            int   i0 = sIdx[t];
            float fr = sFrac[t];
            float v1 = (i0 >= 0 && i0 < TT)      ? row[i0 * 25 + v]      : 0.f;
            float v2 = (i0 >= -1 && i0 < TT - 1) ? row[i0 * 25 + 25 + v] : 0.f;
            float sv = v1 + fr * (v2 - v1);
            s += sv; ss += sv * sv;
        }
    }
    block_reduce2(s, ss);
    if (threadIdx.x == 0) { g_part2[nb][0][o] = s; g_part2[nb][1][o] = ss; }
}
__global__ void bn2_finalize(const float* __restrict__ g2,
                             const float* __restrict__ b2) {
    int o = threadIdx.x;
    float s = 0.f, ss = 0.f;
    for (int nb = 0; nb < NSPLIT; ++nb) { s += g_part2[nb][0][o]; ss += g_part2[nb][1][o]; }
    float mean = s / (float)NTV;
    float var  = ss / (float)NTV - mean * mean;
    float a = g2[o] * rsqrtf(var + 1e-5f);
    g_A2[o] = a;
    g_D2[o] = b2[o] - mean * a;
}

// ---------------- kernel 7: final shift_out + BN2 -> out ------------------------
__global__ void final_kernel(float* __restrict__ out) {
    const int b = blockIdx.x;        // b = n*256 + o
    const int o = b & 255;
    __shared__ int   sIdx[TT];
    __shared__ float sFrac[TT];
    if (threadIdx.x < TT) {
        sIdx[threadIdx.x]  = g_idx_out[o * TT + threadIdx.x];
        sFrac[threadIdx.x] = g_frac_out[o * TT + threadIdx.x];
    }
    __syncthreads();
    const float* row = g_h2 + (size_t)b * TV;
    float* orow = out + (size_t)b * TV;
    const float A = g_A2[o], D = g_D2[o];
    for (int i = threadIdx.x; i < TV; i += 256) {
        int t = i / 25;
        int v = i - t * 25;
        int   i0 = sIdx[t];
        float fr = sFrac[t];
        float v1 = (i0 >= 0 && i0 < TT)      ? row[i0 * 25 + v]      : 0.f;
        float v2 = (i0 >= -1 && i0 < TT - 1) ? row[i0 * 25 + 25 + v] : 0.f;
        float sv = v1 + fr * (v2 - v1);
        orow[i] = A * sv + D;
    }
}

// ---------------- launch ---------------------------------------------------------
extern "C" void kernel_launch(void* const* d_in, const int* in_sizes, int n_in,
                              void* d_out, int out_size) {
    const float* x      = (const float*)d_in[0];
    const float* conv_w = (const float*)d_in[1];
    const float* conv_b = (const float*)d_in[2];
    const float* bn1_g  = (const float*)d_in[3];
    const float* bn1_b  = (const float*)d_in[4];
    const float* bn2_g  = (const float*)d_in[5];
    const float* bn2_b  = (const float*)d_in[6];
    const float* th_in  = (const float*)d_in[7];
    const float* th_out = (const float*)d_in[8];
    float* out = (float*)d_out;

    cudaFuncSetAttribute(gemm_mma,   cudaFuncAttributeMaxDynamicSharedMemorySize, SM_TOTAL);
    cudaFuncSetAttribute(bprep_kernel, cudaFuncAttributeMaxDynamicSharedMemorySize, BP_TOTAL);

    stats_x_kernel<<<dim3(CC, NSPLIT), 256>>>(x);
    bn1_finalize<<<1, 256>>>(bn1_g, bn1_b);
    tables_kernel<<<(CC * TT + 255) / 256, 256>>>(th_in, th_out);
    wprep_kernel<<<OO, 256>>>(conv_w);
    bias_kernel<<<OO, 256>>>(conv_w, conv_b);
    bprep_kernel<<<dim3(TV / 64, NB), 256, BP_TOTAL>>>(x);
    gemm_mma<<<dim3(TV / 64, 2, NB / 8), 256, SM_TOTAL>>>(x);
    stats2_kernel<<<dim3(OO, NSPLIT), 256>>>();
    bn2_finalize<<<1, 256>>>(bn2_g, bn2_b);
    final_kernel<<<NB * OO, 256>>>(out);
}